// round 3
// baseline (speedup 1.0000x reference)
#include <cuda_runtime.h>
#include <math.h>

// Problem constants (shapes fixed by setup_inputs)
#define BATCH   64
#define LEN     256000
#define V4      (LEN / 4)        // 64000 float4 per row
#define CHUNKS  32
#define VC      (V4 / CHUNKS)    // 2000 float4 per chunk
#define THREADS 256
#define NPART   8

// Deterministic scratch (no allocations allowed)
__device__ float g_partials[BATCH * CHUNKS * NPART];

__device__ __forceinline__ float dot4(float4 a, float4 b) {
    return a.x * b.x + a.y * b.y + a.z * b.z + a.w * b.w;
}

__device__ __forceinline__ float warp_sum(float v) {
    #pragma unroll
    for (int off = 16; off >= 1; off >>= 1)
        v += __shfl_xor_sync(0xFFFFFFFFu, v, off);
    return v;
}

__global__ __launch_bounds__(THREADS)
void pit_stage1(const float4* __restrict__ pred,
                const float4* __restrict__ s1,
                const float4* __restrict__ s2) {
    const int bid = blockIdx.x;
    const int b = bid / CHUNKS;
    const int c = bid % CHUNKS;

    const float4* __restrict__ p0 = pred + (size_t)b * V4;
    const float4* __restrict__ p1 = pred + (size_t)(BATCH + b) * V4;
    const float4* __restrict__ t1 = s1 + (size_t)b * V4;
    const float4* __restrict__ t2 = s2 + (size_t)b * V4;

    const int start = c * VC;
    const int end = start + VC;

    float aP0 = 0.f, aP1 = 0.f, aT1 = 0.f, aT2 = 0.f;
    float a01 = 0.f, a02 = 0.f, a11 = 0.f, a12 = 0.f;

    int i = start + threadIdx.x;
    // main loop: 2 indices per iteration -> 8 outstanding 128-bit loads
    for (; i + THREADS < end; i += 2 * THREADS) {
        float4 x0a = p0[i],            x0b = p0[i + THREADS];
        float4 x1a = p1[i],            x1b = p1[i + THREADS];
        float4 y1a = t1[i],            y1b = t1[i + THREADS];
        float4 y2a = t2[i],            y2b = t2[i + THREADS];
        aP0 += dot4(x0a, x0a); aP0 += dot4(x0b, x0b);
        aP1 += dot4(x1a, x1a); aP1 += dot4(x1b, x1b);
        aT1 += dot4(y1a, y1a); aT1 += dot4(y1b, y1b);
        aT2 += dot4(y2a, y2a); aT2 += dot4(y2b, y2b);
        a01 += dot4(x0a, y1a); a01 += dot4(x0b, y1b);
        a02 += dot4(x0a, y2a); a02 += dot4(x0b, y2b);
        a11 += dot4(x1a, y1a); a11 += dot4(x1b, y1b);
        a12 += dot4(x1a, y2a); a12 += dot4(x1b, y2b);
    }
    // tail
    for (; i < end; i += THREADS) {
        float4 x0 = p0[i];
        float4 x1 = p1[i];
        float4 y1 = t1[i];
        float4 y2 = t2[i];
        aP0 += dot4(x0, x0);
        aP1 += dot4(x1, x1);
        aT1 += dot4(y1, y1);
        aT2 += dot4(y2, y2);
        a01 += dot4(x0, y1);
        a02 += dot4(x0, y2);
        a11 += dot4(x1, y1);
        a12 += dot4(x1, y2);
    }

    // warp reduce all 8
    aP0 = warp_sum(aP0); aP1 = warp_sum(aP1);
    aT1 = warp_sum(aT1); aT2 = warp_sum(aT2);
    a01 = warp_sum(a01); a02 = warp_sum(a02);
    a11 = warp_sum(a11); a12 = warp_sum(a12);

    __shared__ float smem[THREADS / 32][NPART];
    const int lane = threadIdx.x & 31;
    const int warp = threadIdx.x >> 5;
    if (lane == 0) {
        smem[warp][0] = aP0; smem[warp][1] = aP1;
        smem[warp][2] = aT1; smem[warp][3] = aT2;
        smem[warp][4] = a01; smem[warp][5] = a02;
        smem[warp][6] = a11; smem[warp][7] = a12;
    }
    __syncthreads();

    if (threadIdx.x < NPART) {
        float s = 0.f;
        #pragma unroll
        for (int w = 0; w < THREADS / 32; w++)
            s += smem[w][threadIdx.x];
        g_partials[(size_t)bid * NPART + threadIdx.x] = s;
    }
}

__device__ __forceinline__ float si_sdr_val(float P, float T, float D) {
    const float EPS = 1.1920929e-07f;  // np.finfo(float32).eps
    float alpha = (D + EPS) / (T + EPS);
    float sig = alpha * alpha * T;
    float noise = P - 2.f * alpha * D + sig;
    return 10.f * log10f((sig + EPS) / (noise + EPS));
}

__global__ void pit_stage2(float* __restrict__ out) {
    __shared__ float ps[BATCH];
    const int b = threadIdx.x;  // 64 threads

    float s[NPART];
    #pragma unroll
    for (int k = 0; k < NPART; k++) s[k] = 0.f;

    #pragma unroll 4
    for (int c = 0; c < CHUNKS; c++) {
        const float* p = &g_partials[((size_t)b * CHUNKS + c) * NPART];
        #pragma unroll
        for (int k = 0; k < NPART; k++) s[k] += p[k];
    }

    const float P0 = s[0], P1 = s[1], T1 = s[2], T2 = s[3];
    const float D01 = s[4], D02 = s[5], D11 = s[6], D12 = s[7];

    // score1: (p0 vs s1) + (p1 vs s2); score2 (flipped): (p1 vs s1) + (p0 vs s2)
    float score1 = 0.5f * (si_sdr_val(P0, T1, D01) + si_sdr_val(P1, T2, D12));
    float score2 = 0.5f * (si_sdr_val(P1, T1, D11) + si_sdr_val(P0, T2, D02));
    ps[b] = fmaxf(score1, score2);
    __syncthreads();

    // tree-sum over 64 values (deterministic)
    #pragma unroll
    for (int off = 32; off >= 1; off >>= 1) {
        if (b < off) ps[b] += ps[b + off];
        __syncthreads();
    }
    if (b == 0) out[0] = -ps[0] / (float)BATCH;
}

extern "C" void kernel_launch(void* const* d_in, const int* in_sizes, int n_in,
                              void* d_out, int out_size) {
    const float4* pred = (const float4*)d_in[0];  // output_audios (2,B,L)
    const float4* s1 = (const float4*)d_in[1];    // s1 (B,L)
    const float4* s2 = (const float4*)d_in[2];    // s2 (B,L)
    float* out = (float*)d_out;

    pit_stage1<<<BATCH * CHUNKS, THREADS>>>(pred, s1, s2);
    pit_stage2<<<1, BATCH>>>(out);
}